// round 2
// baseline (speedup 1.0000x reference)
#include <cuda_runtime.h>
#include <cstddef>

// Problem constants
constexpr int kB  = 4;
constexpr int kC  = 512;
constexpr int kC8 = 64;
constexpr int kN  = 4096;               // 64*64 spatial
constexpr size_t kOutElems = (size_t)kB * kC * kN;      // 8,388,608
// attention follows out in d_out

// Scratch (static device allocations — allowed)
__device__ float g_qk[(size_t)kB * 128 * kN];   // [b][o][n], o<64 = q, o>=64 = k  (8 MB)
__device__ float g_v[(size_t)kB * kC * kN];     // only touched when gamma != 0   (32 MB)
__device__ float g_vout[(size_t)kB * kC * kN];  // only touched when gamma != 0   (32 MB)

// ---------------------------------------------------------------------------
// Kernel 1: Q/K projection.  qk[b][o][n] = sum_c w[o][c]*y[b][c][n] + bias[o]
// Block: 256 threads, tile = 128 outputs x 64 positions. Grid (64, B).
// ---------------------------------------------------------------------------
__global__ __launch_bounds__(256) void proj_qk_kernel(
    const float* __restrict__ y,
    const float* __restrict__ wq, const float* __restrict__ bq,
    const float* __restrict__ wk, const float* __restrict__ bk)
{
    __shared__ __align__(16) float ys[16][64];
    __shared__ __align__(16) float ws[128][16];

    const int b   = blockIdx.y;
    const int n0  = blockIdx.x * 64;
    const int tid = threadIdx.x;
    const int n   = tid & 63;
    const int og  = tid >> 6;   // 0..3 -> 32 outputs each

    float acc[32];
#pragma unroll
    for (int j = 0; j < 32; j++) acc[j] = 0.f;

    const float* yb = y + (size_t)b * kC * kN;

    for (int c0 = 0; c0 < kC; c0 += 16) {
        // load y tile: ys[cc][n'] (coalesced: 64 consecutive n per row)
#pragma unroll
        for (int k = 0; k < 4; k++) {
            int cc = og + k * 4;
            ys[cc][n] = yb[(size_t)(c0 + cc) * kN + n0 + n];
        }
        // load weight tile: ws[o][cc], o in [0,128)
#pragma unroll
        for (int k = 0; k < 8; k++) {
            int l  = tid + k * 256;
            int o  = l >> 4;
            int cc = l & 15;
            float w = (o < 64) ? wq[o * kC + c0 + cc]
                               : wk[(o - 64) * kC + c0 + cc];
            ws[o][cc] = w;
        }
        __syncthreads();

        float yr[16];
#pragma unroll
        for (int cc = 0; cc < 16; cc++) yr[cc] = ys[cc][n];

#pragma unroll
        for (int j = 0; j < 32; j++) {
            const float4* wr = (const float4*)ws[og * 32 + j];
            float4 w0 = wr[0], w1 = wr[1], w2 = wr[2], w3 = wr[3];
            float s = acc[j];
            s += w0.x * yr[0]  + w0.y * yr[1]  + w0.z * yr[2]  + w0.w * yr[3];
            s += w1.x * yr[4]  + w1.y * yr[5]  + w1.z * yr[6]  + w1.w * yr[7];
            s += w2.x * yr[8]  + w2.y * yr[9]  + w2.z * yr[10] + w2.w * yr[11];
            s += w3.x * yr[12] + w3.y * yr[13] + w3.z * yr[14] + w3.w * yr[15];
            acc[j] = s;
        }
        __syncthreads();
    }

    // epilogue with bias
    float* qkb = g_qk + (size_t)b * 128 * kN;
#pragma unroll
    for (int j = 0; j < 32; j++) {
        int o = og * 32 + j;
        float bias = (o < 64) ? bq[o] : bk[o - 64];
        qkb[(size_t)o * kN + n0 + n] = acc[j] + bias;
    }
}

// ---------------------------------------------------------------------------
// Kernel 2: energy[b][m][n] = sum_o Q[o][m] * K[o][n]   (written into attn area)
// Classic 128x128 tile SGEMM, 8x8 per-thread microtile, K-dim = 64.
// Grid (32, 32, B), block 256.
// ---------------------------------------------------------------------------
__global__ __launch_bounds__(256) void energy_kernel(float* __restrict__ attn)
{
    __shared__ __align__(16) float As[8][128];
    __shared__ __align__(16) float Bs[8][128];

    const int b   = blockIdx.z;
    const int m0  = blockIdx.y * 128;
    const int n0  = blockIdx.x * 128;
    const int tid = threadIdx.x;
    const int tx  = tid & 15;
    const int ty  = tid >> 4;

    const float* Q = g_qk + (size_t)b * 128 * kN;        // rows 0..63
    const float* K = Q + (size_t)64 * kN;                // rows 64..127

    const int rowL = tid >> 5;          // 0..7
    const int colL = (tid & 31) * 4;    // 0..124

    float acc[8][8];
#pragma unroll
    for (int i = 0; i < 8; i++)
#pragma unroll
        for (int j = 0; j < 8; j++) acc[i][j] = 0.f;

    for (int k0 = 0; k0 < 64; k0 += 8) {
        *(float4*)&As[rowL][colL] = *(const float4*)&Q[(size_t)(k0 + rowL) * kN + m0 + colL];
        *(float4*)&Bs[rowL][colL] = *(const float4*)&K[(size_t)(k0 + rowL) * kN + n0 + colL];
        __syncthreads();

#pragma unroll
        for (int kk = 0; kk < 8; kk++) {
            float a[8], bb[8];
            *(float4*)&a[0]  = *(const float4*)&As[kk][ty * 8];
            *(float4*)&a[4]  = *(const float4*)&As[kk][ty * 8 + 4];
            *(float4*)&bb[0] = *(const float4*)&Bs[kk][tx * 8];
            *(float4*)&bb[4] = *(const float4*)&Bs[kk][tx * 8 + 4];
#pragma unroll
            for (int i = 0; i < 8; i++)
#pragma unroll
                for (int j = 0; j < 8; j++)
                    acc[i][j] += a[i] * bb[j];
        }
        __syncthreads();
    }

#pragma unroll
    for (int i = 0; i < 8; i++) {
        float* p = attn + ((size_t)b * kN + m0 + ty * 8 + i) * kN + n0 + tx * 8;
        *(float4*)&p[0] = *(const float4*)&acc[i][0];
        *(float4*)&p[4] = *(const float4*)&acc[i][4];
    }
}

// ---------------------------------------------------------------------------
// Kernel 3: in-place row softmax over last dim (4096). One block per row.
// ---------------------------------------------------------------------------
__global__ __launch_bounds__(256) void softmax_kernel(float* __restrict__ attn)
{
    __shared__ float red[8];
    const size_t row = blockIdx.x;          // b*N + m
    float* p = attn + row * kN;
    const int tid = threadIdx.x;

    float v[16];
    float mx = -1e30f;
#pragma unroll
    for (int i = 0; i < 16; i++) {
        v[i] = p[tid + i * 256];
        mx = fmaxf(mx, v[i]);
    }
#pragma unroll
    for (int o = 16; o > 0; o >>= 1) mx = fmaxf(mx, __shfl_xor_sync(0xffffffffu, mx, o));
    if ((tid & 31) == 0) red[tid >> 5] = mx;
    __syncthreads();
    if (tid < 32) {
        float m = (tid < 8) ? red[tid] : -1e30f;
#pragma unroll
        for (int o = 4; o > 0; o >>= 1) m = fmaxf(m, __shfl_xor_sync(0xffffffffu, m, o));
        if (tid == 0) red[0] = m;
    }
    __syncthreads();
    mx = red[0];
    __syncthreads();   // everyone has mx before red is reused

    float s = 0.f;
#pragma unroll
    for (int i = 0; i < 16; i++) {
        v[i] = __expf(v[i] - mx);
        s += v[i];
    }
#pragma unroll
    for (int o = 16; o > 0; o >>= 1) s += __shfl_xor_sync(0xffffffffu, s, o);
    if ((tid & 31) == 0) red[tid >> 5] = s;
    __syncthreads();
    if (tid < 32) {
        float t = (tid < 8) ? red[tid] : 0.f;
#pragma unroll
        for (int o = 4; o > 0; o >>= 1) t += __shfl_xor_sync(0xffffffffu, t, o);
        if (tid == 0) red[0] = t;
    }
    __syncthreads();
    const float inv = 1.0f / red[0];
#pragma unroll
    for (int i = 0; i < 16; i++) p[tid + i * 256] = v[i] * inv;
}

// ---------------------------------------------------------------------------
// Kernel 4: V projection (only when gamma != 0).  v[b][o][n], o in [0,512)
// Grid (64 n-tiles, 4 o-tiles of 128, B).
// ---------------------------------------------------------------------------
__global__ __launch_bounds__(256) void proj_v_kernel(
    const float* __restrict__ x,
    const float* __restrict__ wv, const float* __restrict__ bv,
    const float* __restrict__ gamma)
{
    if (*gamma == 0.0f) return;

    __shared__ __align__(16) float ys[16][64];
    __shared__ __align__(16) float ws[128][16];

    const int b   = blockIdx.z;
    const int ot  = blockIdx.y;          // o-tile base = ot*128
    const int n0  = blockIdx.x * 64;
    const int tid = threadIdx.x;
    const int n   = tid & 63;
    const int og  = tid >> 6;

    float acc[32];
#pragma unroll
    for (int j = 0; j < 32; j++) acc[j] = 0.f;

    const float* xb = x + (size_t)b * kC * kN;
    const float* wbase = wv + (size_t)(ot * 128) * kC;

    for (int c0 = 0; c0 < kC; c0 += 16) {
#pragma unroll
        for (int k = 0; k < 4; k++) {
            int cc = og + k * 4;
            ys[cc][n] = xb[(size_t)(c0 + cc) * kN + n0 + n];
        }
#pragma unroll
        for (int k = 0; k < 8; k++) {
            int l  = tid + k * 256;
            int o  = l >> 4;
            int cc = l & 15;
            ws[o][cc] = wbase[(size_t)o * kC + c0 + cc];
        }
        __syncthreads();

        float yr[16];
#pragma unroll
        for (int cc = 0; cc < 16; cc++) yr[cc] = ys[cc][n];

#pragma unroll
        for (int j = 0; j < 32; j++) {
            const float4* wr = (const float4*)ws[og * 32 + j];
            float4 w0 = wr[0], w1 = wr[1], w2 = wr[2], w3 = wr[3];
            float s = acc[j];
            s += w0.x * yr[0]  + w0.y * yr[1]  + w0.z * yr[2]  + w0.w * yr[3];
            s += w1.x * yr[4]  + w1.y * yr[5]  + w1.z * yr[6]  + w1.w * yr[7];
            s += w2.x * yr[8]  + w2.y * yr[9]  + w2.z * yr[10] + w2.w * yr[11];
            s += w3.x * yr[12] + w3.y * yr[13] + w3.z * yr[14] + w3.w * yr[15];
            acc[j] = s;
        }
        __syncthreads();
    }

    float* vb = g_v + (size_t)b * kC * kN;
#pragma unroll
    for (int j = 0; j < 32; j++) {
        int o = ot * 128 + og * 32 + j;
        vb[(size_t)o * kN + n0 + n] = acc[j] + bv[o];
    }
}

// ---------------------------------------------------------------------------
// Kernel 5: vout[b][c][m] = sum_n v[b][c][n] * attn[b][m][n]  (gamma != 0 only)
// 64x64 tiles, 4x4 per-thread. Grid (64 m-tiles, 8 c-tiles, B).
// ---------------------------------------------------------------------------
__global__ __launch_bounds__(256) void bmm_kernel(
    const float* __restrict__ attn, const float* __restrict__ gamma)
{
    if (*gamma == 0.0f) return;

    __shared__ float vS[64][17];
    __shared__ float aS[64][17];

    const int b   = blockIdx.z;
    const int c0  = blockIdx.y * 64;
    const int m0  = blockIdx.x * 64;
    const int tid = threadIdx.x;
    const int tx  = tid & 15;
    const int ty  = tid >> 4;

    float acc[4][4];
#pragma unroll
    for (int i = 0; i < 4; i++)
#pragma unroll
        for (int j = 0; j < 4; j++) acc[i][j] = 0.f;

    const float* vb = g_v + (size_t)b * kC * kN;
    const float* ab = attn + (size_t)b * kN * kN;

    for (int nc = 0; nc < kN; nc += 16) {
#pragma unroll
        for (int k = 0; k < 4; k++) {
            int l = tid + k * 256;
            int r = l >> 4, cc = l & 15;
            vS[r][cc] = vb[(size_t)(c0 + r) * kN + nc + cc];
            aS[r][cc] = ab[(size_t)(m0 + r) * kN + nc + cc];
        }
        __syncthreads();
#pragma unroll
        for (int kk = 0; kk < 16; kk++) {
            float a[4], bb[4];
#pragma unroll
            for (int i = 0; i < 4; i++) a[i]  = vS[ty * 4 + i][kk];
#pragma unroll
            for (int j = 0; j < 4; j++) bb[j] = aS[tx * 4 + j][kk];
#pragma unroll
            for (int i = 0; i < 4; i++)
#pragma unroll
                for (int j = 0; j < 4; j++) acc[i][j] += a[i] * bb[j];
        }
        __syncthreads();
    }

#pragma unroll
    for (int i = 0; i < 4; i++)
#pragma unroll
        for (int j = 0; j < 4; j++)
            g_vout[((size_t)b * kC + c0 + ty * 4 + i) * kN + m0 + tx * 4 + j] = acc[i][j];
}

// ---------------------------------------------------------------------------
// Kernel 6: out = gamma * vout + x  (fast path gamma==0: pure copy)
// ---------------------------------------------------------------------------
__global__ __launch_bounds__(256) void final_kernel(
    const float* __restrict__ x, const float* __restrict__ gamma,
    float* __restrict__ out)
{
    const float g = *gamma;
    const size_t i = ((size_t)blockIdx.x * 256 + threadIdx.x) * 4;
    float4 xv = *(const float4*)&x[i];
    if (g != 0.f) {
        float4 a = *(const float4*)&g_vout[i];
        xv.x += g * a.x; xv.y += g * a.y; xv.z += g * a.z; xv.w += g * a.w;
    }
    *(float4*)&out[i] = xv;
}

// ---------------------------------------------------------------------------
extern "C" void kernel_launch(void* const* d_in, const int* in_sizes, int n_in,
                              void* d_out, int out_size)
{
    const float* x     = (const float*)d_in[0];
    const float* y     = (const float*)d_in[1];
    const float* wq    = (const float*)d_in[2];
    const float* bq    = (const float*)d_in[3];
    const float* wk    = (const float*)d_in[4];
    const float* bk    = (const float*)d_in[5];
    const float* wv    = (const float*)d_in[6];
    const float* bv    = (const float*)d_in[7];
    const float* gamma = (const float*)d_in[8];

    float* out  = (float*)d_out;
    float* attn = out + kOutElems;   // attention output region, [B][N][N]

    // 1) Q/K projections
    proj_qk_kernel<<<dim3(kN / 64, kB), 256>>>(y, wq, bq, wk, bk);
    // 2) energy = Q^T K  -> written into attention region
    energy_kernel<<<dim3(kN / 128, kN / 128, kB), 256>>>(attn);
    // 3) row softmax in place
    softmax_kernel<<<kB * kN, 256>>>(attn);
    // 4/5) gamma != 0 fallback path (early-exits when gamma == 0)
    proj_v_kernel<<<dim3(kN / 64, 4, kB), 256>>>(x, wv, bv, gamma);
    bmm_kernel<<<dim3(kN / 64, kC / 64, kB), 256>>>(attn, gamma);
    // 6) out = gamma * vout + x
    final_kernel<<<(unsigned)(kOutElems / (256 * 4)), 256>>>(x, gamma, out);
}

// round 3
// speedup vs baseline: 1.1040x; 1.1040x over previous
#include <cuda_runtime.h>
#include <cuda_bf16.h>
#include <cstddef>
#include <cstdint>

// Problem constants
constexpr int kB  = 4;
constexpr int kC  = 512;
constexpr int kN  = 4096;               // 64*64 spatial
constexpr size_t kOutElems = (size_t)kB * kC * kN;      // 8,388,608

// Scratch
__device__ float g_q[(size_t)kB * kN * 64];     // [b][n][o]  (4 MB)  Q transposed
__device__ float g_k[(size_t)kB * 64 * kN];     // [b][o][n]  (4 MB)
__device__ float g_v[(size_t)kB * kC * kN];     // gamma!=0 path only (32 MB)
__device__ float g_vout[(size_t)kB * kC * kN];  // gamma!=0 path only (32 MB)

// ---------------------------------------------------------------------------
// Kernel 1: Q/K projection. q -> g_q[b][n][o] (transposed), k -> g_k[b][o][n]
// ---------------------------------------------------------------------------
__global__ __launch_bounds__(256) void proj_qk_kernel(
    const float* __restrict__ y,
    const float* __restrict__ wq, const float* __restrict__ bq,
    const float* __restrict__ wk, const float* __restrict__ bk)
{
    __shared__ __align__(16) float ys[16][64];
    __shared__ __align__(16) float ws[128][16];

    const int b   = blockIdx.y;
    const int n0  = blockIdx.x * 64;
    const int tid = threadIdx.x;
    const int n   = tid & 63;
    const int og  = tid >> 6;   // 0..3 -> 32 outputs each

    float acc[32];
#pragma unroll
    for (int j = 0; j < 32; j++) acc[j] = 0.f;

    const float* yb = y + (size_t)b * kC * kN;

    for (int c0 = 0; c0 < kC; c0 += 16) {
#pragma unroll
        for (int k = 0; k < 4; k++) {
            int cc = og + k * 4;
            ys[cc][n] = yb[(size_t)(c0 + cc) * kN + n0 + n];
        }
#pragma unroll
        for (int k = 0; k < 8; k++) {
            int l  = tid + k * 256;
            int o  = l >> 4;
            int cc = l & 15;
            float w = (o < 64) ? wq[o * kC + c0 + cc]
                               : wk[(o - 64) * kC + c0 + cc];
            ws[o][cc] = w;
        }
        __syncthreads();

        float yr[16];
#pragma unroll
        for (int cc = 0; cc < 16; cc++) yr[cc] = ys[cc][n];

#pragma unroll
        for (int j = 0; j < 32; j++) {
            const float4* wr = (const float4*)ws[og * 32 + j];
            float4 w0 = wr[0], w1 = wr[1], w2 = wr[2], w3 = wr[3];
            float s = acc[j];
            s += w0.x * yr[0]  + w0.y * yr[1]  + w0.z * yr[2]  + w0.w * yr[3];
            s += w1.x * yr[4]  + w1.y * yr[5]  + w1.z * yr[6]  + w1.w * yr[7];
            s += w2.x * yr[8]  + w2.y * yr[9]  + w2.z * yr[10] + w2.w * yr[11];
            s += w3.x * yr[12] + w3.y * yr[13] + w3.z * yr[14] + w3.w * yr[15];
            acc[j] = s;
        }
        __syncthreads();
    }

#pragma unroll
    for (int j = 0; j < 32; j++) {
        int o = og * 32 + j;
        if (o < 64) {
            g_q[((size_t)b * kN + n0 + n) * 64 + o] = acc[j] + bq[o];
        } else {
            g_k[((size_t)b * 64 + (o - 64)) * kN + n0 + n] = acc[j] + bk[o - 64];
        }
    }
}

// ---------------------------------------------------------------------------
// Kernel 2: energy + exp via bf16 tensor cores (3-product split precision).
// S[m][n] = Q[m][:]. K[:][n];  writes exp(S) into attn.
// Tile 128x128, 256 threads (8 warps, 4x2), k = 64.
// ---------------------------------------------------------------------------
__device__ __forceinline__ void ldm4(uint32_t* r, const __nv_bfloat16* p) {
    uint32_t a = (uint32_t)__cvta_generic_to_shared(p);
    asm volatile("ldmatrix.sync.aligned.m8n8.x4.shared.b16 {%0,%1,%2,%3}, [%4];"
        : "=r"(r[0]), "=r"(r[1]), "=r"(r[2]), "=r"(r[3]) : "r"(a));
}

__device__ __forceinline__ void mma_bf16(float* d, const uint32_t* a, const uint32_t* b) {
    asm volatile(
        "mma.sync.aligned.m16n8k16.row.col.f32.bf16.bf16.f32 "
        "{%0,%1,%2,%3}, {%4,%5,%6,%7}, {%8,%9}, {%0,%1,%2,%3};"
        : "+f"(d[0]), "+f"(d[1]), "+f"(d[2]), "+f"(d[3])
        : "r"(a[0]), "r"(a[1]), "r"(a[2]), "r"(a[3]), "r"(b[0]), "r"(b[1]));
}

constexpr int EPAD = 72;                       // row pad (bf16 elems) for ldmatrix
constexpr size_t kEnergySmem = (size_t)4 * 128 * EPAD * sizeof(__nv_bfloat16); // 73728

__global__ __launch_bounds__(256) void energy_kernel(float* __restrict__ attn)
{
    extern __shared__ __nv_bfloat16 sm[];
    __nv_bfloat16* a_hi = sm;
    __nv_bfloat16* a_lo = a_hi + 128 * EPAD;
    __nv_bfloat16* b_hi = a_lo + 128 * EPAD;
    __nv_bfloat16* b_lo = b_hi + 128 * EPAD;

    const int b   = blockIdx.z;
    const int m0  = blockIdx.y * 128;
    const int n0  = blockIdx.x * 128;
    const int tid = threadIdx.x;
    const int lane = tid & 31;
    const int warp = tid >> 5;
    const int wr = warp >> 1;       // 0..3
    const int wc = warp & 1;        // 0..1
    const int mwarp = wr * 32;

    // --- load & split A (Q tile: 128 rows x 64) ---
    const float* Qb = g_q + ((size_t)b * kN + m0) * 64;
#pragma unroll
    for (int i = 0; i < 8; i++) {
        int idx4 = tid + i * 256;            // 0..2047
        int r = idx4 >> 4, c4 = (idx4 & 15) * 4;
        float4 v = *(const float4*)&Qb[r * 64 + c4];
        float f[4] = {v.x, v.y, v.z, v.w};
#pragma unroll
        for (int d = 0; d < 4; d++) {
            __nv_bfloat16 h = __float2bfloat16(f[d]);
            a_hi[r * EPAD + c4 + d] = h;
            a_lo[r * EPAD + c4 + d] = __float2bfloat16(f[d] - __bfloat162float(h));
        }
    }
    // --- load & split B (K tile transposed into [n][k]) ---
    const float* Kb = g_k + (size_t)b * 64 * kN + n0;
#pragma unroll
    for (int i = 0; i < 8; i++) {
        int idx4 = tid + i * 256;
        int o = idx4 >> 5, n4 = (idx4 & 31) * 4;
        float4 v = *(const float4*)&Kb[(size_t)o * kN + n4];
        float f[4] = {v.x, v.y, v.z, v.w};
#pragma unroll
        for (int d = 0; d < 4; d++) {
            __nv_bfloat16 h = __float2bfloat16(f[d]);
            b_hi[(n4 + d) * EPAD + o] = h;
            b_lo[(n4 + d) * EPAD + o] = __float2bfloat16(f[d] - __bfloat162float(h));
        }
    }
    __syncthreads();

    float acc[2][8][4];
#pragma unroll
    for (int i = 0; i < 2; i++)
#pragma unroll
        for (int j = 0; j < 8; j++)
#pragma unroll
            for (int d = 0; d < 4; d++) acc[i][j][d] = 0.f;

    const int t8 = lane >> 3, lr = lane & 7;

#pragma unroll
    for (int ks = 0; ks < 4; ks++) {
        const int k0 = ks * 16;
        uint32_t ah[2][4], al[2][4];
#pragma unroll
        for (int i = 0; i < 2; i++) {
            const __nv_bfloat16* pa =
                &a_hi[(mwarp + i * 16 + (t8 & 1) * 8 + lr) * EPAD + k0 + (t8 >> 1) * 8];
            ldm4(ah[i], pa);
            ldm4(al[i], pa + 128 * EPAD);   // a_lo
        }
#pragma unroll
        for (int jj = 0; jj < 4; jj++) {
            const __nv_bfloat16* pb =
                &b_hi[(wc * 64 + jj * 16 + (t8 >> 1) * 8 + lr) * EPAD + k0 + (t8 & 1) * 8];
            uint32_t bh[4], bl[4];
            ldm4(bh, pb);
            ldm4(bl, pb + 128 * EPAD);      // b_lo
#pragma unroll
            for (int i = 0; i < 2; i++) {
#pragma unroll
                for (int jt = 0; jt < 2; jt++) {
                    float* d = acc[i][jj * 2 + jt];
                    mma_bf16(d, ah[i], bh + 2 * jt);
                    mma_bf16(d, ah[i], bl + 2 * jt);
                    mma_bf16(d, al[i], bh + 2 * jt);
                }
            }
        }
    }

    // --- epilogue: exp and store ---
    float* ab = attn + (size_t)b * kN * kN;
    const int rbase = m0 + mwarp + (lane >> 2);
    const int cbase = n0 + wc * 64 + 2 * (lane & 3);
#pragma unroll
    for (int i = 0; i < 2; i++) {
        const int r = rbase + i * 16;
#pragma unroll
        for (int j = 0; j < 8; j++) {
            const int c = cbase + j * 8;
            float2 v0 = {__expf(acc[i][j][0]), __expf(acc[i][j][1])};
            float2 v1 = {__expf(acc[i][j][2]), __expf(acc[i][j][3])};
            *(float2*)&ab[(size_t)r * kN + c]       = v0;
            *(float2*)&ab[(size_t)(r + 8) * kN + c] = v1;
        }
    }
}

// ---------------------------------------------------------------------------
// Kernel 3: normalize rows: p[i] /= sum(p). One block per row of 4096.
// ---------------------------------------------------------------------------
__global__ __launch_bounds__(256) void normalize_kernel(float* __restrict__ attn)
{
    __shared__ float red[8];
    float* p = attn + blockIdx.x * (size_t)kN;
    const int tid = threadIdx.x;

    float v[16];
    float s = 0.f;
#pragma unroll
    for (int i = 0; i < 16; i++) {
        v[i] = p[tid + i * 256];
        s += v[i];
    }
#pragma unroll
    for (int o = 16; o > 0; o >>= 1) s += __shfl_xor_sync(0xffffffffu, s, o);
    if ((tid & 31) == 0) red[tid >> 5] = s;
    __syncthreads();
    if (tid < 32) {
        float t = (tid < 8) ? red[tid] : 0.f;
#pragma unroll
        for (int o = 4; o > 0; o >>= 1) t += __shfl_xor_sync(0xffffffffu, t, o);
        if (tid == 0) red[0] = t;
    }
    __syncthreads();
    const float inv = 1.0f / red[0];
#pragma unroll
    for (int i = 0; i < 16; i++) p[tid + i * 256] = v[i] * inv;
}

// ---------------------------------------------------------------------------
// Kernel 4: V projection (gamma != 0 only).
// ---------------------------------------------------------------------------
__global__ __launch_bounds__(256) void proj_v_kernel(
    const float* __restrict__ x,
    const float* __restrict__ wv, const float* __restrict__ bv,
    const float* __restrict__ gamma)
{
    if (*gamma == 0.0f) return;

    __shared__ __align__(16) float ys[16][64];
    __shared__ __align__(16) float ws[128][16];

    const int b   = blockIdx.z;
    const int ot  = blockIdx.y;
    const int n0  = blockIdx.x * 64;
    const int tid = threadIdx.x;
    const int n   = tid & 63;
    const int og  = tid >> 6;

    float acc[32];
#pragma unroll
    for (int j = 0; j < 32; j++) acc[j] = 0.f;

    const float* xb = x + (size_t)b * kC * kN;
    const float* wbase = wv + (size_t)(ot * 128) * kC;

    for (int c0 = 0; c0 < kC; c0 += 16) {
#pragma unroll
        for (int k = 0; k < 4; k++) {
            int cc = og + k * 4;
            ys[cc][n] = xb[(size_t)(c0 + cc) * kN + n0 + n];
        }
#pragma unroll
        for (int k = 0; k < 8; k++) {
            int l  = tid + k * 256;
            int o  = l >> 4;
            int cc = l & 15;
            ws[o][cc] = wbase[(size_t)o * kC + c0 + cc];
        }
        __syncthreads();

        float yr[16];
#pragma unroll
        for (int cc = 0; cc < 16; cc++) yr[cc] = ys[cc][n];

#pragma unroll
        for (int j = 0; j < 32; j++) {
            const float4* wr = (const float4*)ws[og * 32 + j];
            float4 w0 = wr[0], w1 = wr[1], w2 = wr[2], w3 = wr[3];
            float s = acc[j];
            s += w0.x * yr[0]  + w0.y * yr[1]  + w0.z * yr[2]  + w0.w * yr[3];
            s += w1.x * yr[4]  + w1.y * yr[5]  + w1.z * yr[6]  + w1.w * yr[7];
            s += w2.x * yr[8]  + w2.y * yr[9]  + w2.z * yr[10] + w2.w * yr[11];
            s += w3.x * yr[12] + w3.y * yr[13] + w3.z * yr[14] + w3.w * yr[15];
            acc[j] = s;
        }
        __syncthreads();
    }

    float* vb = g_v + (size_t)b * kC * kN;
#pragma unroll
    for (int j = 0; j < 32; j++) {
        int o = ot * 128 + og * 32 + j;
        vb[(size_t)o * kN + n0 + n] = acc[j] + bv[o];
    }
}

// ---------------------------------------------------------------------------
// Kernel 5: vout = v @ attn^T (gamma != 0 only)
// ---------------------------------------------------------------------------
__global__ __launch_bounds__(256) void bmm_kernel(
    const float* __restrict__ attn, const float* __restrict__ gamma)
{
    if (*gamma == 0.0f) return;

    __shared__ float vS[64][17];
    __shared__ float aS[64][17];

    const int b   = blockIdx.z;
    const int c0  = blockIdx.y * 64;
    const int m0  = blockIdx.x * 64;
    const int tid = threadIdx.x;
    const int tx  = tid & 15;
    const int ty  = tid >> 4;

    float acc[4][4];
#pragma unroll
    for (int i = 0; i < 4; i++)
#pragma unroll
        for (int j = 0; j < 4; j++) acc[i][j] = 0.f;

    const float* vb = g_v + (size_t)b * kC * kN;
    const float* ab = attn + (size_t)b * kN * kN;

    for (int nc = 0; nc < kN; nc += 16) {
#pragma unroll
        for (int k = 0; k < 4; k++) {
            int l = tid + k * 256;
            int r = l >> 4, cc = l & 15;
            vS[r][cc] = vb[(size_t)(c0 + r) * kN + nc + cc];
            aS[r][cc] = ab[(size_t)(m0 + r) * kN + nc + cc];
        }
        __syncthreads();
#pragma unroll
        for (int kk = 0; kk < 16; kk++) {
            float a[4], bb[4];
#pragma unroll
            for (int i = 0; i < 4; i++) a[i]  = vS[ty * 4 + i][kk];
#pragma unroll
            for (int j = 0; j < 4; j++) bb[j] = aS[tx * 4 + j][kk];
#pragma unroll
            for (int i = 0; i < 4; i++)
#pragma unroll
                for (int j = 0; j < 4; j++) acc[i][j] += a[i] * bb[j];
        }
        __syncthreads();
    }

#pragma unroll
    for (int i = 0; i < 4; i++)
#pragma unroll
        for (int j = 0; j < 4; j++)
            g_vout[((size_t)b * kC + c0 + ty * 4 + i) * kN + m0 + tx * 4 + j] = acc[i][j];
}

// ---------------------------------------------------------------------------
// Kernel 6: out = gamma * vout + x  (fast path gamma==0: pure copy)
// ---------------------------------------------------------------------------
__global__ __launch_bounds__(256) void final_kernel(
    const float* __restrict__ x, const float* __restrict__ gamma,
    float* __restrict__ out)
{
    const float g = *gamma;
    const size_t i = ((size_t)blockIdx.x * 256 + threadIdx.x) * 4;
    float4 xv = *(const float4*)&x[i];
    if (g != 0.f) {
        float4 a = *(const float4*)&g_vout[i];
        xv.x += g * a.x; xv.y += g * a.y; xv.z += g * a.z; xv.w += g * a.w;
    }
    *(float4*)&out[i] = xv;
}

// ---------------------------------------------------------------------------
extern "C" void kernel_launch(void* const* d_in, const int* in_sizes, int n_in,
                              void* d_out, int out_size)
{
    const float* x     = (const float*)d_in[0];
    const float* y     = (const float*)d_in[1];
    const float* wq    = (const float*)d_in[2];
    const float* bq    = (const float*)d_in[3];
    const float* wk    = (const float*)d_in[4];
    const float* bk    = (const float*)d_in[5];
    const float* wv    = (const float*)d_in[6];
    const float* bv    = (const float*)d_in[7];
    const float* gamma = (const float*)d_in[8];

    float* out  = (float*)d_out;
    float* attn = out + kOutElems;   // attention output region, [B][N][N]

    cudaFuncSetAttribute(energy_kernel,
                         cudaFuncAttributeMaxDynamicSharedMemorySize,
                         (int)kEnergySmem);

    proj_qk_kernel<<<dim3(kN / 64, kB), 256>>>(y, wq, bq, wk, bk);
    energy_kernel<<<dim3(kN / 128, kN / 128, kB), 256, kEnergySmem>>>(attn);
    normalize_kernel<<<kB * kN, 256>>>(attn);
    proj_v_kernel<<<dim3(kN / 64, 4, kB), 256>>>(x, wv, bv, gamma);
    bmm_kernel<<<dim3(kN / 64, kC / 64, kB), 256>>>(attn, gamma);
    final_kernel<<<(unsigned)(kOutElems / (256 * 4)), 256>>>(x, gamma, out);
}

// round 9
// speedup vs baseline: 1.2733x; 1.1533x over previous
#include <cuda_runtime.h>
#include <cuda_bf16.h>
#include <cstddef>
#include <cstdint>

// Problem constants
constexpr int kB  = 4;
constexpr int kC  = 512;
constexpr int kN  = 4096;               // 64*64 spatial
constexpr size_t kOutElems = (size_t)kB * kC * kN;      // 8,388,608

// Scratch: pre-split bf16 hi/lo Q and K, K-major [b][n][64]
__device__ __nv_bfloat16 g_qh[(size_t)kB * kN * 64];
__device__ __nv_bfloat16 g_ql[(size_t)kB * kN * 64];
__device__ __nv_bfloat16 g_kh[(size_t)kB * kN * 64];
__device__ __nv_bfloat16 g_kl[(size_t)kB * kN * 64];
__device__ float g_partial[(size_t)kB * 32 * kN];   // row-sum partials [b][ntile][m] (8 MB)
__device__ float g_v[(size_t)kB * kC * kN];     // gamma!=0 path only (32 MB)
__device__ float g_vout[(size_t)kB * kC * kN];  // gamma!=0 path only (32 MB)

// ---------------------------------------------------------------------------
// Kernel 1: Q/K projection -> bf16 hi/lo split outputs.
// ---------------------------------------------------------------------------
__global__ __launch_bounds__(256) void proj_qk_kernel(
    const float* __restrict__ y,
    const float* __restrict__ wq, const float* __restrict__ bq,
    const float* __restrict__ wk, const float* __restrict__ bk)
{
    __shared__ __align__(16) float ys[16][64];
    __shared__ __align__(16) float ws[128][16];

    const int b   = blockIdx.y;
    const int n0  = blockIdx.x * 64;
    const int tid = threadIdx.x;
    const int n   = tid & 63;
    const int og  = tid >> 6;

    float acc[32];
#pragma unroll
    for (int j = 0; j < 32; j++) acc[j] = 0.f;

    const float* yb = y + (size_t)b * kC * kN;

    for (int c0 = 0; c0 < kC; c0 += 16) {
#pragma unroll
        for (int k = 0; k < 4; k++) {
            int cc = og + k * 4;
            ys[cc][n] = yb[(size_t)(c0 + cc) * kN + n0 + n];
        }
#pragma unroll
        for (int k = 0; k < 8; k++) {
            int l  = tid + k * 256;
            int o  = l >> 4;
            int cc = l & 15;
            float w = (o < 64) ? wq[o * kC + c0 + cc]
                               : wk[(o - 64) * kC + c0 + cc];
            ws[o][cc] = w;
        }
        __syncthreads();

        float yr[16];
#pragma unroll
        for (int cc = 0; cc < 16; cc++) yr[cc] = ys[cc][n];

#pragma unroll
        for (int j = 0; j < 32; j++) {
            const float4* wr = (const float4*)ws[og * 32 + j];
            float4 w0 = wr[0], w1 = wr[1], w2 = wr[2], w3 = wr[3];
            float s = acc[j];
            s += w0.x * yr[0]  + w0.y * yr[1]  + w0.z * yr[2]  + w0.w * yr[3];
            s += w1.x * yr[4]  + w1.y * yr[5]  + w1.z * yr[6]  + w1.w * yr[7];
            s += w2.x * yr[8]  + w2.y * yr[9]  + w2.z * yr[10] + w2.w * yr[11];
            s += w3.x * yr[12] + w3.y * yr[13] + w3.z * yr[14] + w3.w * yr[15];
            acc[j] = s;
        }
        __syncthreads();
    }

    const size_t rowbase = ((size_t)b * kN + n0 + n) * 64;
#pragma unroll
    for (int j = 0; j < 32; j++) {
        int o = og * 32 + j;
        if (o < 64) {
            float f = acc[j] + bq[o];
            __nv_bfloat16 h = __float2bfloat16(f);
            g_qh[rowbase + o] = h;
            g_ql[rowbase + o] = __float2bfloat16(f - __bfloat162float(h));
        } else {
            float f = acc[j] + bk[o - 64];
            __nv_bfloat16 h = __float2bfloat16(f);
            g_kh[rowbase + (o - 64)] = h;
            g_kl[rowbase + (o - 64)] = __float2bfloat16(f - __bfloat162float(h));
        }
    }
}

// ---------------------------------------------------------------------------
// Kernel 2: energy via bf16 mma.sync (3-product split precision), two passes.
//   pass 0: exp + deterministic per-block row sums -> g_partial (no attn store)
//   pass 1: recompute (bit-identical), scale by 1/rowsum, write attn ONCE.
// ---------------------------------------------------------------------------
__device__ __forceinline__ void ldm4(uint32_t* r, const __nv_bfloat16* p) {
    uint32_t a = (uint32_t)__cvta_generic_to_shared(p);
    asm volatile("ldmatrix.sync.aligned.m8n8.x4.shared.b16 {%0,%1,%2,%3}, [%4];"
        : "=r"(r[0]), "=r"(r[1]), "=r"(r[2]), "=r"(r[3]) : "r"(a));
}
__device__ __forceinline__ void mma_bf16(float* d, const uint32_t* a, const uint32_t* b) {
    asm volatile(
        "mma.sync.aligned.m16n8k16.row.col.f32.bf16.bf16.f32 "
        "{%0,%1,%2,%3}, {%4,%5,%6,%7}, {%8,%9}, {%0,%1,%2,%3};"
        : "+f"(d[0]), "+f"(d[1]), "+f"(d[2]), "+f"(d[3])
        : "r"(a[0]), "r"(a[1]), "r"(a[2]), "r"(a[3]), "r"(b[0]), "r"(b[1]));
}

constexpr int EPAD = 72;                       // padded row (bf16) for ldmatrix
constexpr int kStgStride = 132;                // fp32 staging stride (528B, 16B-aligned)
constexpr size_t kEnergySmem = (size_t)4 * 128 * EPAD * sizeof(__nv_bfloat16); // 73728

__global__ __launch_bounds__(256) void energy_kernel(float* __restrict__ attn, int pass)
{
    extern __shared__ __nv_bfloat16 sm[];
    __nv_bfloat16* a_hi = sm;
    __nv_bfloat16* a_lo = a_hi + 128 * EPAD;
    __nv_bfloat16* b_hi = a_lo + 128 * EPAD;
    __nv_bfloat16* b_lo = b_hi + 128 * EPAD;

    const int b    = blockIdx.z;
    const int m0   = blockIdx.y * 128;
    const int n0   = blockIdx.x * 128;
    const int tid  = threadIdx.x;
    const int lane = tid & 31;
    const int warp = tid >> 5;
    const int wr   = warp >> 1;       // 0..3
    const int wc   = warp & 1;        // 0..1
    const int mwarp = wr * 32;

    // ---- copy pre-split bf16 tiles into padded smem ----
    {
        const __nv_bfloat16* srcs[4] = {
            g_qh + ((size_t)b * kN + m0) * 64,
            g_ql + ((size_t)b * kN + m0) * 64,
            g_kh + ((size_t)b * kN + n0) * 64,
            g_kl + ((size_t)b * kN + n0) * 64 };
        __nv_bfloat16* dsts[4] = { a_hi, a_lo, b_hi, b_lo };
#pragma unroll
        for (int t = 0; t < 4; t++) {
            const uint4* src = (const uint4*)srcs[t];
            __nv_bfloat16* dst = dsts[t];
#pragma unroll
            for (int i = 0; i < 4; i++) {
                int idx = tid + i * 256;          // uint4 index, 0..1023
                int r = idx >> 3, c8 = (idx & 7) * 8;
                *(uint4*)&dst[r * EPAD + c8] = src[idx];
            }
        }
    }
    __syncthreads();

    float acc[2][8][4];
#pragma unroll
    for (int i = 0; i < 2; i++)
#pragma unroll
        for (int j = 0; j < 8; j++)
#pragma unroll
            for (int d = 0; d < 4; d++) acc[i][j][d] = 0.f;

    const int t8 = lane >> 3, lr = lane & 7;

#pragma unroll
    for (int ks = 0; ks < 4; ks++) {
        const int k0 = ks * 16;
        uint32_t ah[2][4], al[2][4];
#pragma unroll
        for (int i = 0; i < 2; i++) {
            const __nv_bfloat16* pa =
                &a_hi[(mwarp + i * 16 + (t8 & 1) * 8 + lr) * EPAD + k0 + (t8 >> 1) * 8];
            ldm4(ah[i], pa);
            ldm4(al[i], pa + 128 * EPAD);   // a_lo
        }
#pragma unroll
        for (int jj = 0; jj < 4; jj++) {
            const __nv_bfloat16* pb =
                &b_hi[(wc * 64 + jj * 16 + (t8 >> 1) * 8 + lr) * EPAD + k0 + (t8 & 1) * 8];
            uint32_t bh[4], bl[4];
            ldm4(bh, pb);
            ldm4(bl, pb + 128 * EPAD);      // b_lo
#pragma unroll
            for (int i = 0; i < 2; i++) {
#pragma unroll
                for (int jt = 0; jt < 2; jt++) {
                    float* d = acc[i][jj * 2 + jt];
                    mma_bf16(d, ah[i], bh + 2 * jt);
                    mma_bf16(d, ah[i], bl + 2 * jt);
                    mma_bf16(d, al[i], bh + 2 * jt);
                }
            }
        }
    }

    __syncthreads();   // tiles consumed; smem free for reuse

    // Thread fragment rows: mwarp + (lane>>2) + 16*i + 8*u  (u = d>>1)
    // cols: wc*64 + j*8 + 2*(lane&3) + (d&1)
    if (pass == 0) {
        // ---- per-thread exp partial sums -> warp shfl -> smem -> g_partial ----
        float p[2][2];
#pragma unroll
        for (int i = 0; i < 2; i++)
#pragma unroll
            for (int u = 0; u < 2; u++) {
                float s = 0.f;
#pragma unroll
                for (int j = 0; j < 8; j++)
                    s += __expf(acc[i][j][2 * u]) + __expf(acc[i][j][2 * u + 1]);
                p[i][u] = s;
            }
        // reduce over lane&3 subgroup (same row)
#pragma unroll
        for (int o = 1; o <= 2; o <<= 1) {
#pragma unroll
            for (int i = 0; i < 2; i++)
#pragma unroll
                for (int u = 0; u < 2; u++)
                    p[i][u] += __shfl_xor_sync(0xffffffffu, p[i][u], o);
        }
        float* sumbuf = (float*)sm;      // [2][128]
        if ((lane & 3) == 0) {
            int rbase = mwarp + (lane >> 2);
#pragma unroll
            for (int i = 0; i < 2; i++)
#pragma unroll
                for (int u = 0; u < 2; u++)
                    sumbuf[wc * 128 + rbase + i * 16 + u * 8] = p[i][u];
        }
        __syncthreads();
        if (tid < 128) {
            g_partial[((size_t)b * 32 + blockIdx.x) * kN + m0 + tid] =
                sumbuf[tid] + sumbuf[128 + tid];
        }
    } else {
        // ---- rowsum from partials (deterministic), scale, single write ----
        float* stg    = (float*)sm;                  // 128 x 132 floats
        float* rowinv = stg + 128 * kStgStride;      // 128 floats @ 67584 B
        if (tid < 128) {
            const float* pp = g_partial + (size_t)b * 32 * kN + m0 + tid;
            float s = 0.f;
#pragma unroll
            for (int j = 0; j < 32; j++) s += pp[(size_t)j * kN];
            rowinv[tid] = 1.0f / s;
        }
        __syncthreads();

        const int rloc = mwarp + (lane >> 2);
        const int cloc = wc * 64 + 2 * (lane & 3);
#pragma unroll
        for (int i = 0; i < 2; i++) {
            const int r = rloc + i * 16;
            const float inv0 = rowinv[r];
            const float inv1 = rowinv[r + 8];
#pragma unroll
            for (int j = 0; j < 8; j++) {
                const int c = cloc + j * 8;
                stg[(size_t)r * kStgStride + c]           = __expf(acc[i][j][0]) * inv0;
                stg[(size_t)r * kStgStride + c + 1]       = __expf(acc[i][j][1]) * inv0;
                stg[(size_t)(r + 8) * kStgStride + c]     = __expf(acc[i][j][2]) * inv1;
                stg[(size_t)(r + 8) * kStgStride + c + 1] = __expf(acc[i][j][3]) * inv1;
            }
        }
        __syncthreads();

        float* ab = attn + (size_t)b * kN * kN;
#pragma unroll
        for (int it = 0; it < 16; it++) {
            int r  = it * 8 + warp;
            int c4 = lane * 4;
            *(float4*)&ab[(size_t)(m0 + r) * kN + n0 + c4] =
                *(const float4*)&stg[r * kStgStride + c4];
        }
    }
}

// ---------------------------------------------------------------------------
// Kernel 4: V projection (gamma != 0 only).
// ---------------------------------------------------------------------------
__global__ __launch_bounds__(256) void proj_v_kernel(
    const float* __restrict__ x,
    const float* __restrict__ wv, const float* __restrict__ bv,
    const float* __restrict__ gamma)
{
    if (*gamma == 0.0f) return;

    __shared__ __align__(16) float ys[16][64];
    __shared__ __align__(16) float ws[128][16];

    const int b   = blockIdx.z;
    const int ot  = blockIdx.y;
    const int n0  = blockIdx.x * 64;
    const int tid = threadIdx.x;
    const int n   = tid & 63;
    const int og  = tid >> 6;

    float acc[32];
#pragma unroll
    for (int j = 0; j < 32; j++) acc[j] = 0.f;

    const float* xb = x + (size_t)b * kC * kN;
    const float* wbase = wv + (size_t)(ot * 128) * kC;

    for (int c0 = 0; c0 < kC; c0 += 16) {
#pragma unroll
        for (int k = 0; k < 4; k++) {
            int cc = og + k * 4;
            ys[cc][n] = xb[(size_t)(c0 + cc) * kN + n0 + n];
        }
#pragma unroll
        for (int k = 0; k < 8; k++) {
            int l  = tid + k * 256;
            int o  = l >> 4;
            int cc = l & 15;
            ws[o][cc] = wbase[(size_t)o * kC + c0 + cc];
        }
        __syncthreads();

        float yr[16];
#pragma unroll
        for (int cc = 0; cc < 16; cc++) yr[cc] = ys[cc][n];

#pragma unroll
        for (int j = 0; j < 32; j++) {
            const float4* wr = (const float4*)ws[og * 32 + j];
            float4 w0 = wr[0], w1 = wr[1], w2 = wr[2], w3 = wr[3];
            float s = acc[j];
            s += w0.x * yr[0]  + w0.y * yr[1]  + w0.z * yr[2]  + w0.w * yr[3];
            s += w1.x * yr[4]  + w1.y * yr[5]  + w1.z * yr[6]  + w1.w * yr[7];
            s += w2.x * yr[8]  + w2.y * yr[9]  + w2.z * yr[10] + w2.w * yr[11];
            s += w3.x * yr[12] + w3.y * yr[13] + w3.z * yr[14] + w3.w * yr[15];
            acc[j] = s;
        }
        __syncthreads();
    }

    float* vb = g_v + (size_t)b * kC * kN;
#pragma unroll
    for (int j = 0; j < 32; j++) {
        int o = ot * 128 + og * 32 + j;
        vb[(size_t)o * kN + n0 + n] = acc[j] + bv[o];
    }
}

// ---------------------------------------------------------------------------
// Kernel 5: vout = v @ attn^T (gamma != 0 only)
// ---------------------------------------------------------------------------
__global__ __launch_bounds__(256) void bmm_kernel(
    const float* __restrict__ attn, const float* __restrict__ gamma)
{
    if (*gamma == 0.0f) return;

    __shared__ float vS[64][17];
    __shared__ float aS[64][17];

    const int b   = blockIdx.z;
    const int c0  = blockIdx.y * 64;
    const int m0  = blockIdx.x * 64;
    const int tid = threadIdx.x;
    const int tx  = tid & 15;
    const int ty  = tid >> 4;

    float acc[4][4];
#pragma unroll
    for (int i = 0; i < 4; i++)
#pragma unroll
        for (int j = 0; j < 4; j++) acc[i][j] = 0.f;

    const float* vb = g_v + (size_t)b * kC * kN;
    const float* ab = attn + (size_t)b * kN * kN;

    for (int nc = 0; nc < kN; nc += 16) {
#pragma unroll
        for (int k = 0; k < 4; k++) {
            int l = tid + k * 256;
            int r = l >> 4, cc = l & 15;
            vS[r][cc] = vb[(size_t)(c0 + r) * kN + nc + cc];
            aS[r][cc] = ab[(size_t)(m0 + r) * kN + nc + cc];
        }
        __syncthreads();
#pragma unroll
        for (int kk = 0; kk < 16; kk++) {
            float a[4], bb[4];
#pragma unroll
            for (int i = 0; i < 4; i++) a[i]  = vS[ty * 4 + i][kk];
#pragma unroll
            for (int j = 0; j < 4; j++) bb[j] = aS[tx * 4 + j][kk];
#pragma unroll
            for (int i = 0; i < 4; i++)
#pragma unroll
                for (int j = 0; j < 4; j++) acc[i][j] += a[i] * bb[j];
        }
        __syncthreads();
    }

#pragma unroll
    for (int i = 0; i < 4; i++)
#pragma unroll
        for (int j = 0; j < 4; j++)
            g_vout[((size_t)b * kC + c0 + ty * 4 + i) * kN + m0 + tx * 4 + j] = acc[i][j];
}

// ---------------------------------------------------------------------------
// Kernel 6: out = gamma * vout + x  (fast path gamma==0: pure copy)
// ---------------------------------------------------------------------------
__global__ __launch_bounds__(256) void final_kernel(
    const float* __restrict__ x, const float* __restrict__ gamma,
    float* __restrict__ out)
{
    const float g = *gamma;
    const size_t i = ((size_t)blockIdx.x * 256 + threadIdx.x) * 4;
    float4 xv = *(const float4*)&x[i];
    if (g != 0.f) {
        float4 a = *(const float4*)&g_vout[i];
        xv.x += g * a.x; xv.y += g * a.y; xv.z += g * a.z; xv.w += g * a.w;
    }
    *(float4*)&out[i] = xv;
}

// ---------------------------------------------------------------------------
extern "C" void kernel_launch(void* const* d_in, const int* in_sizes, int n_in,
                              void* d_out, int out_size)
{
    const float* x     = (const float*)d_in[0];
    const float* y     = (const float*)d_in[1];
    const float* wq    = (const float*)d_in[2];
    const float* bq    = (const float*)d_in[3];
    const float* wk    = (const float*)d_in[4];
    const float* bk    = (const float*)d_in[5];
    const float* wv    = (const float*)d_in[6];
    const float* bv    = (const float*)d_in[7];
    const float* gamma = (const float*)d_in[8];

    float* out  = (float*)d_out;
    float* attn = out + kOutElems;   // attention output region, [B][N][N]

    cudaFuncSetAttribute(energy_kernel,
                         cudaFuncAttributeMaxDynamicSharedMemorySize,
                         (int)kEnergySmem);

    proj_qk_kernel<<<dim3(kN / 64, kB), 256>>>(y, wq, bq, wk, bk);
    energy_kernel<<<dim3(kN / 128, kN / 128, kB), 256, kEnergySmem>>>(attn, 0);
    energy_kernel<<<dim3(kN / 128, kN / 128, kB), 256, kEnergySmem>>>(attn, 1);
    proj_v_kernel<<<dim3(kN / 64, 4, kB), 256>>>(x, wv, bv, gamma);
    bmm_kernel<<<dim3(kN / 64, kC / 64, kB), 256>>>(attn, gamma);
    final_kernel<<<(unsigned)(kOutElems / (256 * 4)), 256>>>(x, gamma, out);
}